// round 14
// baseline (speedup 1.0000x reference)
#include <cuda_runtime.h>
#include <cuda_fp16.h>

#define NMAX   100000
#define EMAX   1600000
#define HDIM   32
#define STRIDE 64                              // padded-CSR slots per node

// Scratch (allocation-free rule: __device__ globals).
// Invariant: g_deg and g_ovfn are zero at every kernel_launch entry
// (module-load zero-init; mm1 restores after consuming them).
__device__ int    g_deg[NMAX];                 // in-degree (excl. self-loop)
__device__ int    g_degc[NMAX];                // degree copy for agg
__device__ float  g_dis[NMAX];                 // rsqrt(deg+1)
__device__ int    g_csrp[(size_t)NMAX * STRIDE]; // padded CSR: src indices
__device__ int    g_ovfn;                      // overflow count (build)
__device__ int    g_ovfc;                      // overflow count (stable copy)
__device__ int2   g_ovf[EMAX];                 // overflow (dst, src)
__device__ __half g_tmp[(size_t)NMAX * HDIM];  // layer-1 messages: dis*(x@W1)
__device__ __half g_tmp2[(size_t)NMAX * HDIM]; // layer-2 messages: dis*(h1@W2)

// int64 read of an int32 buffer fuses two indices -> out of [0,n) w.h.p.
__device__ __forceinline__ int detect_is32(const void* ei, int n, int* s_is32) {
    if (threadIdx.x < 32) {
        long long v = ((const long long*)ei)[threadIdx.x];
        unsigned m = __ballot_sync(0xffffffffu, v < 0 || v >= (long long)n);
        if (threadIdx.x == 0) *s_is32 = m ? 1 : 0;
    }
    __syncthreads();
    return *s_is32;
}

// ---------------- build: degree histogram + padded-CSR fill in ONE pass ----------------

__global__ void build_kernel(const void* __restrict__ ei, int e, int n) {
    __shared__ int s_is32;
    int is32 = detect_is32(ei, n, &s_is32);
    int i = blockIdx.x * blockDim.x + threadIdx.x;
    if (i >= e) return;
    int s, d;
    if (is32) {
        const int* p = (const int*)ei;
        s = p[i]; d = p[e + i];
    } else {
        const long long* p = (const long long*)ei;
        s = (int)p[i]; d = (int)p[e + i];
    }
    int pos = atomicAdd(&g_deg[d], 1);         // rank = slot (any perm ok)
    if (pos < STRIDE) {
        g_csrp[(size_t)d * STRIDE + pos] = s;
    } else {                                   // ~never on this dataset
        int k = atomicAdd(&g_ovfn, 1);
        g_ovf[k] = make_int2(d, s);
    }
}

// ---------------- mm1 (+ node prep fused): tmp = dis * (x @ W1), fp16 ----------------
// 2 threads per node (j-halves of 16). Computes dis from g_deg in-kernel,
// stores dis/degc, restores the g_deg/g_ovfn zero invariant.

__global__ void __launch_bounds__(256)
mm1_kernel(const float* __restrict__ in, const float* __restrict__ W,
           __half* __restrict__ tmp, int n)
{
    __shared__ float Ws[32][32];
    int t = threadIdx.x;
    for (int i = t; i < 1024; i += 256) Ws[i >> 5][i & 31] = W[i];
    __syncthreads();

    if (blockIdx.x == 0 && t == 0) { g_ovfc = g_ovfn; g_ovfn = 0; }

    int node = blockIdx.x * 128 + (t >> 1);
    int half = t & 1;                      // output j-range: half*16 .. half*16+15
    if (node >= n) return;

    int degv = g_deg[node];
    float dn = rsqrtf((float)(degv + 1));  // +1: self-loop
    if (half == 0) {
        g_dis[node]  = dn;
        g_degc[node] = degv;
        g_deg[node]  = 0;                  // restore invariant for next call
    }

    float xr[32];
    const float4* xin = reinterpret_cast<const float4*>(in + (size_t)node * HDIM);
#pragma unroll
    for (int q = 0; q < 8; q++) {
        float4 v = xin[q];
        xr[4 * q + 0] = v.x; xr[4 * q + 1] = v.y;
        xr[4 * q + 2] = v.z; xr[4 * q + 3] = v.w;
    }

    int jb = half * 16;
    float o[16];
#pragma unroll
    for (int j = 0; j < 16; j++) o[j] = 0.0f;
#pragma unroll
    for (int k = 0; k < 32; k++) {
        float xv = xr[k];
#pragma unroll
        for (int j = 0; j < 16; j++) o[j] = fmaf(xv, Ws[k][jb + j], o[j]);
    }

    uint4 u0, u1;
    {
        __half2 h0 = __floats2half2_rn(o[0] * dn,  o[1] * dn);
        __half2 h1 = __floats2half2_rn(o[2] * dn,  o[3] * dn);
        __half2 h2 = __floats2half2_rn(o[4] * dn,  o[5] * dn);
        __half2 h3 = __floats2half2_rn(o[6] * dn,  o[7] * dn);
        u0.x = *reinterpret_cast<unsigned*>(&h0);
        u0.y = *reinterpret_cast<unsigned*>(&h1);
        u0.z = *reinterpret_cast<unsigned*>(&h2);
        u0.w = *reinterpret_cast<unsigned*>(&h3);
        __half2 g0 = __floats2half2_rn(o[8] * dn,  o[9] * dn);
        __half2 g1 = __floats2half2_rn(o[10] * dn, o[11] * dn);
        __half2 g2 = __floats2half2_rn(o[12] * dn, o[13] * dn);
        __half2 g3 = __floats2half2_rn(o[14] * dn, o[15] * dn);
        u1.x = *reinterpret_cast<unsigned*>(&g0);
        u1.y = *reinterpret_cast<unsigned*>(&g1);
        u1.z = *reinterpret_cast<unsigned*>(&g2);
        u1.w = *reinterpret_cast<unsigned*>(&g3);
    }
    uint4* tp = reinterpret_cast<uint4*>(tmp + (size_t)node * HDIM + jb);
    tp[0] = u0;
    tp[1] = u1;
}

// ---------------- shared agg phase: gather + accumulate (fp32 chains) ----------------
// 8-lane group per node, lane = 4 features. Explicit MLP-8 front-batching.

__device__ __forceinline__ void agg_row(const uint2* __restrict__ tmp4,
                                        int node, int li,
                                        float2& a0, float2& a1)
{
    int deg = g_degc[node];
    int end = deg < STRIDE ? deg : STRIDE;
    const int* row = g_csrp + (size_t)node * STRIDE;

    uint2 sv = __ldg(&tmp4[(size_t)node * 8 + li]);        // self-loop term
    a0 = __half22float2(*reinterpret_cast<__half2*>(&sv.x));
    a1 = __half22float2(*reinterpret_cast<__half2*>(&sv.y));

    int k = 0;
    for (; k + 8 <= end; k += 8) {         // full batches: explicit MLP=8
        int ss[8];
#pragma unroll
        for (int j = 0; j < 8; j++) ss[j] = __ldg(&row[k + j]);
        uint2 v[8];
#pragma unroll
        for (int j = 0; j < 8; j++) v[j] = __ldg(&tmp4[(size_t)ss[j] * 8 + li]);
#pragma unroll
        for (int j = 0; j < 8; j++) {
            float2 v0 = __half22float2(*reinterpret_cast<__half2*>(&v[j].x));
            float2 v1 = __half22float2(*reinterpret_cast<__half2*>(&v[j].y));
            a0.x += v0.x; a0.y += v0.y;
            a1.x += v1.x; a1.y += v1.y;
        }
    }
    for (; k < end; k++) {                 // tail, independent iterations
        int ss = __ldg(&row[k]);
        uint2 v = __ldg(&tmp4[(size_t)ss * 8 + li]);
        float2 v0 = __half22float2(*reinterpret_cast<__half2*>(&v.x));
        float2 v1 = __half22float2(*reinterpret_cast<__half2*>(&v.y));
        a0.x += v0.x; a0.y += v0.y;
        a1.x += v1.x; a1.y += v1.y;
    }

    if (deg > STRIDE) {                    // overflow path: ~never taken
        int c = g_ovfc;
        for (int i = 0; i < c; i++) {
            int2 o = g_ovf[i];
            if (o.x == node) {
                uint2 v = __ldg(&tmp4[(size_t)o.y * 8 + li]);
                float2 v0 = __half22float2(*reinterpret_cast<__half2*>(&v.x));
                float2 v1 = __half22float2(*reinterpret_cast<__half2*>(&v.y));
                a0.x += v0.x; a0.y += v0.y;
                a1.x += v1.x; a1.y += v1.y;
            }
        }
    }
}

// ---------------- fused agg1 + mm2: h1 = relu(dis*agg + b1); tmp2 = dis*(h1 @ W2) ----
// Block = 32 nodes. Phase 1 aggregates into smem rows (fp32), phase 2 does the
// 32x32 GEMM from smem and emits fp16 layer-2 messages. No global h1 buffer.

__global__ void __launch_bounds__(256)
aggmm_kernel(const uint2* __restrict__ tmp4, const float* __restrict__ W2,
             const float* __restrict__ b1, __half* __restrict__ tmp2, int n)
{
    __shared__ float Ws[32][32];
    __shared__ float bs[32];
    __shared__ float xs[32][33];           // 32 node rows, padded
    int t = threadIdx.x;
    for (int i = t; i < 1024; i += 256) Ws[i >> 5][i & 31] = W2[i];
    if (t < 32) bs[t] = b1[t];

    int nl   = t >> 3;                     // node-local 0..31
    int li   = t & 7;
    int node = blockIdx.x * 32 + nl;
    bool valid = node < n;
    int cnode = valid ? node : (n - 1);

    float2 a0, a1;
    agg_row(tmp4, cnode, li, a0, a1);

    float dn = g_dis[cnode];
    int jb = li * 4;
    xs[nl][jb + 0] = fmaxf(a0.x * dn + bs[jb + 0], 0.0f);
    xs[nl][jb + 1] = fmaxf(a0.y * dn + bs[jb + 1], 0.0f);
    xs[nl][jb + 2] = fmaxf(a1.x * dn + bs[jb + 2], 0.0f);
    xs[nl][jb + 3] = fmaxf(a1.y * dn + bs[jb + 3], 0.0f);
    __syncthreads();

    // phase 2: o[j] = sum_k xs[nl][k] * W2[k][j], j in jb..jb+3
    float o0 = 0.0f, o1 = 0.0f, o2 = 0.0f, o3 = 0.0f;
#pragma unroll
    for (int k = 0; k < 32; k++) {
        float xv = xs[nl][k];
        float4 w = *reinterpret_cast<const float4*>(&Ws[k][jb]);
        o0 = fmaf(xv, w.x, o0);
        o1 = fmaf(xv, w.y, o1);
        o2 = fmaf(xv, w.z, o2);
        o3 = fmaf(xv, w.w, o3);
    }

    if (!valid) return;
    __half2 h0 = __floats2half2_rn(o0 * dn, o1 * dn);
    __half2 h1 = __floats2half2_rn(o2 * dn, o3 * dn);
    uint2 u;
    u.x = *reinterpret_cast<unsigned*>(&h0);
    u.y = *reinterpret_cast<unsigned*>(&h1);
    reinterpret_cast<uint2*>(tmp2)[(size_t)node * 8 + li] = u;
}

// ---------------- agg2: out = relu(dis*agg(tmp2) + b2), fp32 ----------------

__global__ void __launch_bounds__(256)
agg2_kernel(const uint2* __restrict__ tmp4, float* __restrict__ out,
            const float* __restrict__ b, int n)
{
    int gid  = blockIdx.x * 256 + threadIdx.x;
    int node = gid >> 3;
    int li   = threadIdx.x & 7;
    if (node >= n) return;

    float2 a0, a1;
    agg_row(tmp4, node, li, a0, a1);

    float dn = g_dis[node];
    float4 bb = reinterpret_cast<const float4*>(b)[li];
    float4 r = make_float4(fmaxf(a0.x * dn + bb.x, 0.0f),
                           fmaxf(a0.y * dn + bb.y, 0.0f),
                           fmaxf(a1.x * dn + bb.z, 0.0f),
                           fmaxf(a1.y * dn + bb.w, 0.0f));
    reinterpret_cast<float4*>(out)[(size_t)node * 8 + li] = r;
}

// ---------------- launch ----------------

extern "C" void kernel_launch(void* const* d_in, const int* in_sizes, int n_in,
                              void* d_out, int out_size)
{
    const float* x   = (const float*)d_in[0];
    const void*  ei  = d_in[1];
    const float* W1  = (const float*)d_in[2];
    const float* b1  = (const float*)d_in[3];
    const float* W2  = (const float*)d_in[4];
    const float* b2  = (const float*)d_in[5];
    float*       out = (float*)d_out;

    int n = in_sizes[0] / HDIM;       // 100000
    int e = in_sizes[1] / 2;          // 1600000

    void *p_tmp, *p_tmp2;
    cudaGetSymbolAddress(&p_tmp,  g_tmp);
    cudaGetSymbolAddress(&p_tmp2, g_tmp2);
    uint2*  tmp4  = (uint2*)p_tmp;
    __half* tmp   = (__half*)p_tmp;
    uint2*  tmp24 = (uint2*)p_tmp2;
    __half* tmp2  = (__half*)p_tmp2;

    int nb_e = (e + 255) / 256;
    int nb_m = (n + 127) / 128;               // 2 threads per node
    int nb_f = (n + 31) / 32;                 // 32 nodes per fused block
    int nb_g = (n * 8 + 255) / 256;           // 8 lanes per node

    build_kernel<<<nb_e, 256>>>(ei, e, n);                    // CSR + degrees
    mm1_kernel  <<<nb_m, 256>>>(x, W1, tmp, n);               // + node prep fused
    aggmm_kernel<<<nb_f, 256>>>(tmp4, W2, b1, tmp2, n);       // agg1 + mm2 fused
    agg2_kernel <<<nb_g, 256>>>(tmp24, out, b2, n);           // final layer
}

// round 15
// speedup vs baseline: 1.0785x; 1.0785x over previous
#include <cuda_runtime.h>
#include <cuda_fp16.h>

#define NMAX   100000
#define EMAX   1600000
#define HDIM   32
#define STRIDE 64                              // padded-CSR slots per node

// Scratch (allocation-free rule: __device__ globals).
// Invariant: g_deg and g_ovfn are zero at every kernel_launch entry
// (module-load zero-init; mm1 restores after consuming them).
__device__ int    g_deg[NMAX];                 // in-degree (excl. self-loop)
__device__ int    g_degc[NMAX];                // degree copy for agg
__device__ float  g_dis[NMAX];                 // rsqrt(deg+1)
__device__ int    g_csrp[(size_t)NMAX * STRIDE]; // padded CSR: src indices
__device__ int    g_ovfn;                      // overflow count (build)
__device__ int    g_ovfc;                      // overflow count (stable copy)
__device__ int2   g_ovf[EMAX];                 // overflow (dst, src)
__device__ __half g_tmp[(size_t)NMAX * HDIM];  // messages: dis*(f(in)@W), fp16
__device__ __half g_acc16[(size_t)NMAX * HDIM];// layer-1 output, fp16

// int64 read of an int32 buffer fuses two indices -> out of [0,n) w.h.p.
__device__ __forceinline__ int detect_is32(const void* ei, int n, int* s_is32) {
    if (threadIdx.x < 32) {
        long long v = ((const long long*)ei)[threadIdx.x];
        unsigned m = __ballot_sync(0xffffffffu, v < 0 || v >= (long long)n);
        if (threadIdx.x == 0) *s_is32 = m ? 1 : 0;
    }
    __syncthreads();
    return *s_is32;
}

// ---------------- build: degree histogram + padded-CSR fill in ONE pass ----------------

__global__ void build_kernel(const void* __restrict__ ei, int e, int n) {
    __shared__ int s_is32;
    int is32 = detect_is32(ei, n, &s_is32);
    int i = blockIdx.x * blockDim.x + threadIdx.x;
    if (i >= e) return;
    int s, d;
    if (is32) {
        const int* p = (const int*)ei;
        s = p[i]; d = p[e + i];
    } else {
        const long long* p = (const long long*)ei;
        s = (int)p[i]; d = (int)p[e + i];
    }
    int pos = atomicAdd(&g_deg[d], 1);         // rank = slot (any perm ok)
    if (pos < STRIDE) {
        g_csrp[(size_t)d * STRIDE + pos] = s;
    } else {                                   // ~never on this dataset
        int k = atomicAdd(&g_ovfn, 1);
        g_ovf[k] = make_int2(d, s);
    }
}

// ---------------- mm1 (+ node prep fused): tmp = dis * (x @ W1), fp16 ----------------
// 2 threads per node (j-halves of 16). Computes dis from g_deg in-kernel,
// stores dis/degc, restores the g_deg/g_ovfn zero invariant.

__global__ void __launch_bounds__(256)
mm1_kernel(const float* __restrict__ in, const float* __restrict__ W,
           __half* __restrict__ tmp, int n)
{
    __shared__ float Ws[32][32];
    int t = threadIdx.x;
    for (int i = t; i < 1024; i += 256) Ws[i >> 5][i & 31] = W[i];
    __syncthreads();

    if (blockIdx.x == 0 && t == 0) { g_ovfc = g_ovfn; g_ovfn = 0; }

    int node = blockIdx.x * 128 + (t >> 1);
    int half = t & 1;
    if (node >= n) return;

    int degv = g_deg[node];
    float dn = rsqrtf((float)(degv + 1));  // +1: self-loop
    if (half == 0) {
        g_dis[node]  = dn;
        g_degc[node] = degv;
        g_deg[node]  = 0;                  // restore invariant for next call
    }

    float xr[32];
    const float4* xin = reinterpret_cast<const float4*>(in + (size_t)node * HDIM);
#pragma unroll
    for (int q = 0; q < 8; q++) {
        float4 v = xin[q];
        xr[4 * q + 0] = v.x; xr[4 * q + 1] = v.y;
        xr[4 * q + 2] = v.z; xr[4 * q + 3] = v.w;
    }

    int jb = half * 16;
    float o[16];
#pragma unroll
    for (int j = 0; j < 16; j++) o[j] = 0.0f;
#pragma unroll
    for (int k = 0; k < 32; k++) {
        float xv = xr[k];
#pragma unroll
        for (int j = 0; j < 16; j++) o[j] = fmaf(xv, Ws[k][jb + j], o[j]);
    }

    uint4 u0, u1;
    {
        __half2 h0 = __floats2half2_rn(o[0] * dn,  o[1] * dn);
        __half2 h1 = __floats2half2_rn(o[2] * dn,  o[3] * dn);
        __half2 h2 = __floats2half2_rn(o[4] * dn,  o[5] * dn);
        __half2 h3 = __floats2half2_rn(o[6] * dn,  o[7] * dn);
        u0.x = *reinterpret_cast<unsigned*>(&h0);
        u0.y = *reinterpret_cast<unsigned*>(&h1);
        u0.z = *reinterpret_cast<unsigned*>(&h2);
        u0.w = *reinterpret_cast<unsigned*>(&h3);
        __half2 g0 = __floats2half2_rn(o[8] * dn,  o[9] * dn);
        __half2 g1 = __floats2half2_rn(o[10] * dn, o[11] * dn);
        __half2 g2 = __floats2half2_rn(o[12] * dn, o[13] * dn);
        __half2 g3 = __floats2half2_rn(o[14] * dn, o[15] * dn);
        u1.x = *reinterpret_cast<unsigned*>(&g0);
        u1.y = *reinterpret_cast<unsigned*>(&g1);
        u1.z = *reinterpret_cast<unsigned*>(&g2);
        u1.w = *reinterpret_cast<unsigned*>(&g3);
    }
    uint4* tp = reinterpret_cast<uint4*>(tmp + (size_t)node * HDIM + jb);
    tp[0] = u0;
    tp[1] = u1;
}

// ---------------- mm2: tmp = dis * (relu(acc16 + b1) @ W2), fp16 ----------------
// 2 threads per node, fp16 input rows.

__global__ void __launch_bounds__(256)
mm2_kernel(const __half* __restrict__ in, const float* __restrict__ W,
           const float* __restrict__ b, __half* __restrict__ tmp, int n)
{
    __shared__ float Ws[32][32];
    __shared__ float bs[32];
    int t = threadIdx.x;
    for (int i = t; i < 1024; i += 256) Ws[i >> 5][i & 31] = W[i];
    if (t < 32) bs[t] = b[t];
    __syncthreads();

    int node = blockIdx.x * 128 + (t >> 1);
    int half = t & 1;
    if (node >= n) return;

    float xr[32];
    const uint4* xin = reinterpret_cast<const uint4*>(in + (size_t)node * HDIM);
#pragma unroll
    for (int q = 0; q < 4; q++) {
        uint4 u = xin[q];
        unsigned w[4] = {u.x, u.y, u.z, u.w};
#pragma unroll
        for (int j = 0; j < 4; j++) {
            float2 f = __half22float2(*reinterpret_cast<__half2*>(&w[j]));
            xr[q * 8 + j * 2 + 0] = f.x;
            xr[q * 8 + j * 2 + 1] = f.y;
        }
    }
#pragma unroll
    for (int j = 0; j < 32; j++) xr[j] = fmaxf(xr[j] + bs[j], 0.0f);

    int jb = half * 16;
    float o[16];
#pragma unroll
    for (int j = 0; j < 16; j++) o[j] = 0.0f;
#pragma unroll
    for (int k = 0; k < 32; k++) {
        float xv = xr[k];
#pragma unroll
        for (int j = 0; j < 16; j++) o[j] = fmaf(xv, Ws[k][jb + j], o[j]);
    }

    float dn = g_dis[node];
    uint4 u0, u1;
    {
        __half2 h0 = __floats2half2_rn(o[0] * dn,  o[1] * dn);
        __half2 h1 = __floats2half2_rn(o[2] * dn,  o[3] * dn);
        __half2 h2 = __floats2half2_rn(o[4] * dn,  o[5] * dn);
        __half2 h3 = __floats2half2_rn(o[6] * dn,  o[7] * dn);
        u0.x = *reinterpret_cast<unsigned*>(&h0);
        u0.y = *reinterpret_cast<unsigned*>(&h1);
        u0.z = *reinterpret_cast<unsigned*>(&h2);
        u0.w = *reinterpret_cast<unsigned*>(&h3);
        __half2 g0 = __floats2half2_rn(o[8] * dn,  o[9] * dn);
        __half2 g1 = __floats2half2_rn(o[10] * dn, o[11] * dn);
        __half2 g2 = __floats2half2_rn(o[12] * dn, o[13] * dn);
        __half2 g3 = __floats2half2_rn(o[14] * dn, o[15] * dn);
        u1.x = *reinterpret_cast<unsigned*>(&g0);
        u1.y = *reinterpret_cast<unsigned*>(&g1);
        u1.z = *reinterpret_cast<unsigned*>(&g2);
        u1.w = *reinterpret_cast<unsigned*>(&g3);
    }
    uint4* tp = reinterpret_cast<uint4*>(tmp + (size_t)node * HDIM + jb);
    tp[0] = u0;
    tp[1] = u1;
}

// ---------------- aggregate (pure gather, padded CSR, fp16 msgs) ----------------
// 4 nodes per warp: 8-lane group per node, lane = 4 features (uint2 of half2s).
// Indices loaded as 2 x int4 (vs 8 scalar LDGs). Full batches front-load all 8
// gathers (explicit MLP=8), then 4 independent fp32 accumulation chains.
// OUT16: write fp16 row without bias (layer 1). Else fp32 + bias + relu.

template <bool OUT16>
__global__ void __launch_bounds__(256)
agg_kernel(const uint2* __restrict__ tmp4, void* __restrict__ out,
           const float* __restrict__ b, int n)
{
    int gid  = blockIdx.x * 256 + threadIdx.x;
    int node = gid >> 3;
    int li   = threadIdx.x & 7;
    if (node >= n) return;               // no shfl -> free exit

    int deg = g_degc[node];
    int end = deg < STRIDE ? deg : STRIDE;
    const int* row = g_csrp + (size_t)node * STRIDE;

    uint2 sv = __ldg(&tmp4[(size_t)node * 8 + li]);        // self-loop term
    float2 a0 = __half22float2(*reinterpret_cast<__half2*>(&sv.x));
    float2 a1 = __half22float2(*reinterpret_cast<__half2*>(&sv.y));

    int k = 0;
    // full batches: vectorized index loads + explicit gather front-batching
    for (; k + 8 <= end; k += 8) {
        int4 sa = __ldg(reinterpret_cast<const int4*>(&row[k]));
        int4 sb = __ldg(reinterpret_cast<const int4*>(&row[k + 4]));
        int ss[8] = {sa.x, sa.y, sa.z, sa.w, sb.x, sb.y, sb.z, sb.w};
        uint2 v[8];
#pragma unroll
        for (int j = 0; j < 8; j++) v[j] = __ldg(&tmp4[(size_t)ss[j] * 8 + li]);
#pragma unroll
        for (int j = 0; j < 8; j++) {
            float2 v0 = __half22float2(*reinterpret_cast<__half2*>(&v[j].x));
            float2 v1 = __half22float2(*reinterpret_cast<__half2*>(&v[j].y));
            a0.x += v0.x; a0.y += v0.y;
            a1.x += v1.x; a1.y += v1.y;
        }
    }
    // tail (0..7 edges), iterations independent
    for (; k < end; k++) {
        int ss = __ldg(&row[k]);
        uint2 v = __ldg(&tmp4[(size_t)ss * 8 + li]);
        float2 v0 = __half22float2(*reinterpret_cast<__half2*>(&v.x));
        float2 v1 = __half22float2(*reinterpret_cast<__half2*>(&v.y));
        a0.x += v0.x; a0.y += v0.y;
        a1.x += v1.x; a1.y += v1.y;
    }

    if (deg > STRIDE) {                  // overflow path: ~never taken
        int c = g_ovfc;
        for (int i = 0; i < c; i++) {
            int2 o = g_ovf[i];
            if (o.x == node) {
                uint2 v = __ldg(&tmp4[(size_t)o.y * 8 + li]);
                float2 v0 = __half22float2(*reinterpret_cast<__half2*>(&v.x));
                float2 v1 = __half22float2(*reinterpret_cast<__half2*>(&v.y));
                a0.x += v0.x; a0.y += v0.y;
                a1.x += v1.x; a1.y += v1.y;
            }
        }
    }

    float dn = g_dis[node];
    if (OUT16) {
        __half2 h0 = __floats2half2_rn(a0.x * dn, a0.y * dn);
        __half2 h1 = __floats2half2_rn(a1.x * dn, a1.y * dn);
        uint2 u;
        u.x = *reinterpret_cast<unsigned*>(&h0);
        u.y = *reinterpret_cast<unsigned*>(&h1);
        reinterpret_cast<uint2*>(out)[(size_t)node * 8 + li] = u;
    } else {
        float4 bb = reinterpret_cast<const float4*>(b)[li];
        float4 r = make_float4(fmaxf(a0.x * dn + bb.x, 0.0f),
                               fmaxf(a0.y * dn + bb.y, 0.0f),
                               fmaxf(a1.x * dn + bb.z, 0.0f),
                               fmaxf(a1.y * dn + bb.w, 0.0f));
        reinterpret_cast<float4*>(out)[(size_t)node * 8 + li] = r;
    }
}

// ---------------- launch ----------------

extern "C" void kernel_launch(void* const* d_in, const int* in_sizes, int n_in,
                              void* d_out, int out_size)
{
    const float* x   = (const float*)d_in[0];
    const void*  ei  = d_in[1];
    const float* W1  = (const float*)d_in[2];
    const float* b1  = (const float*)d_in[3];
    const float* W2  = (const float*)d_in[4];
    const float* b2  = (const float*)d_in[5];
    float*       out = (float*)d_out;

    int n = in_sizes[0] / HDIM;       // 100000
    int e = in_sizes[1] / 2;          // 1600000

    void *p_tmp, *p_acc;
    cudaGetSymbolAddress(&p_tmp, g_tmp);
    cudaGetSymbolAddress(&p_acc, g_acc16);
    uint2*  tmp4  = (uint2*)p_tmp;
    __half* tmp   = (__half*)p_tmp;
    __half* acc16 = (__half*)p_acc;

    int nb_e = (e + 255) / 256;
    int nb_m = (n + 127) / 128;               // 2 threads per node
    int nb_g = (n * 8 + 255) / 256;           // 8 lanes per node

    build_kernel    <<<nb_e, 256>>>(ei, e, n);            // CSR + degrees
    mm1_kernel      <<<nb_m, 256>>>(x, W1, tmp, n);       // + node prep fused
    agg_kernel<true><<<nb_g, 256>>>(tmp4, acc16, nullptr, n);
    mm2_kernel      <<<nb_m, 256>>>(acc16, W2, b1, tmp, n);
    agg_kernel<false><<<nb_g, 256>>>(tmp4, out, b2, n);
}

// round 16
// speedup vs baseline: 1.1070x; 1.0264x over previous
#include <cuda_runtime.h>
#include <cuda_fp16.h>

#define NMAX   100000
#define EMAX   1600000
#define HDIM   32
#define STRIDE 64                              // padded-CSR slots per node

// Scratch (allocation-free rule: __device__ globals).
// Invariant: g_deg and g_ovfn are zero at every kernel_launch entry
// (module-load zero-init; mm1 restores after consuming them).
__device__ int    g_deg[NMAX];                 // in-degree (excl. self-loop)
__device__ int    g_degc[NMAX];                // degree copy for agg
__device__ float  g_dis[NMAX];                 // rsqrt(deg+1)
__device__ int    g_csrp[(size_t)NMAX * STRIDE]; // padded CSR: src indices
__device__ int    g_ovfn;                      // overflow count (build)
__device__ int    g_ovfc;                      // overflow count (stable copy)
__device__ int2   g_ovf[EMAX];                 // overflow (dst, src)
__device__ __half g_tmp[(size_t)NMAX * HDIM];  // messages: dis*(row@W), fp16
__device__ __half g_acc16[(size_t)NMAX * HDIM];// layer-1 output relu(..)+b1, fp16

// int64 read of an int32 buffer fuses two indices -> out of [0,n) w.h.p.
__device__ __forceinline__ int detect_is32(const void* ei, int n, int* s_is32) {
    if (threadIdx.x < 32) {
        long long v = ((const long long*)ei)[threadIdx.x];
        unsigned m = __ballot_sync(0xffffffffu, v < 0 || v >= (long long)n);
        if (threadIdx.x == 0) *s_is32 = m ? 1 : 0;
    }
    __syncthreads();
    return *s_is32;
}

// ---------------- build: degree histogram + padded-CSR fill in ONE pass ----------------

__global__ void build_kernel(const void* __restrict__ ei, int e, int n) {
    __shared__ int s_is32;
    int is32 = detect_is32(ei, n, &s_is32);
    int i = blockIdx.x * blockDim.x + threadIdx.x;
    if (i >= e) return;
    int s, d;
    if (is32) {
        const int* p = (const int*)ei;
        s = p[i]; d = p[e + i];
    } else {
        const long long* p = (const long long*)ei;
        s = (int)p[i]; d = (int)p[e + i];
    }
    int pos = atomicAdd(&g_deg[d], 1);         // rank = slot (any perm ok)
    if (pos < STRIDE) {
        g_csrp[(size_t)d * STRIDE + pos] = s;
    } else {                                   // ~never on this dataset
        int k = atomicAdd(&g_ovfn, 1);
        g_ovf[k] = make_int2(d, s);
    }
}

// ---------------- mm: tmp[node] = dis[node] * (row @ W), fp16 out ----------------
// Block = 128 nodes. Rows staged in smem (coalesced), then 2 threads/node
// (j-halves of 16) compute from smem: regs ~34 -> full occupancy.
// IN16: fp16 input rows. PREP: fused node prep (dis from g_deg, invariant restore).

template <bool IN16, bool PREP>
__global__ void __launch_bounds__(256)
mm_kernel(const void* __restrict__ in, const float* __restrict__ W,
          __half* __restrict__ tmp, int n)
{
    __shared__ float Ws[32][32];
    __shared__ float xs[128][36];          // stride 36 floats: 16B-aligned rows
    int t = threadIdx.x;
    for (int i = t; i < 1024; i += 256) Ws[i >> 5][i & 31] = W[i];

    if (PREP && blockIdx.x == 0 && t == 0) { g_ovfc = g_ovfn; g_ovfn = 0; }

    int base   = blockIdx.x * 128;
    int nvalid = n - base;
    if (nvalid > 128) nvalid = 128;

    // stage rows
    if (IN16) {
        const uint4* xin = reinterpret_cast<const uint4*>((const __half*)in + (size_t)base * HDIM);
        for (int i = t; i < nvalid * 4; i += 256) {   // 4 x uint4 per row
            int row = i >> 2, col = (i & 3) * 8;
            uint4 u = xin[i];
            unsigned w[4] = {u.x, u.y, u.z, u.w};
            float f[8];
#pragma unroll
            for (int j = 0; j < 4; j++) {
                float2 p = __half22float2(*reinterpret_cast<__half2*>(&w[j]));
                f[2 * j] = p.x; f[2 * j + 1] = p.y;
            }
            *reinterpret_cast<float4*>(&xs[row][col])     = make_float4(f[0], f[1], f[2], f[3]);
            *reinterpret_cast<float4*>(&xs[row][col + 4]) = make_float4(f[4], f[5], f[6], f[7]);
        }
    } else {
        const float4* xin = reinterpret_cast<const float4*>((const float*)in + (size_t)base * HDIM);
        for (int i = t; i < nvalid * 8; i += 256) {   // 8 x float4 per row
            int row = i >> 3, col = (i & 7) * 4;
            *reinterpret_cast<float4*>(&xs[row][col]) = xin[i];
        }
    }
    __syncthreads();

    int nl   = t >> 1;
    int half = t & 1;
    if (nl >= nvalid) return;
    int node = base + nl;

    float dn;
    if (PREP) {
        int degv = g_deg[node];
        dn = rsqrtf((float)(degv + 1));    // +1: self-loop
        if (half == 0) {
            g_dis[node]  = dn;
            g_degc[node] = degv;
            g_deg[node]  = 0;              // restore invariant for next call
        }
    } else {
        dn = g_dis[node];
    }

    int jb = half * 16;
    float o[16];
#pragma unroll
    for (int j = 0; j < 16; j++) o[j] = 0.0f;
#pragma unroll
    for (int k = 0; k < 32; k += 4) {
        float4 xq = *reinterpret_cast<const float4*>(&xs[nl][k]);
        float xv[4] = {xq.x, xq.y, xq.z, xq.w};
#pragma unroll
        for (int q = 0; q < 4; q++) {
#pragma unroll
            for (int j = 0; j < 16; j++)
                o[j] = fmaf(xv[q], Ws[k + q][jb + j], o[j]);
        }
    }

    uint4 u0, u1;
    {
        __half2 h0 = __floats2half2_rn(o[0] * dn,  o[1] * dn);
        __half2 h1 = __floats2half2_rn(o[2] * dn,  o[3] * dn);
        __half2 h2 = __floats2half2_rn(o[4] * dn,  o[5] * dn);
        __half2 h3 = __floats2half2_rn(o[6] * dn,  o[7] * dn);
        u0.x = *reinterpret_cast<unsigned*>(&h0);
        u0.y = *reinterpret_cast<unsigned*>(&h1);
        u0.z = *reinterpret_cast<unsigned*>(&h2);
        u0.w = *reinterpret_cast<unsigned*>(&h3);
        __half2 g0 = __floats2half2_rn(o[8] * dn,  o[9] * dn);
        __half2 g1 = __floats2half2_rn(o[10] * dn, o[11] * dn);
        __half2 g2 = __floats2half2_rn(o[12] * dn, o[13] * dn);
        __half2 g3 = __floats2half2_rn(o[14] * dn, o[15] * dn);
        u1.x = *reinterpret_cast<unsigned*>(&g0);
        u1.y = *reinterpret_cast<unsigned*>(&g1);
        u1.z = *reinterpret_cast<unsigned*>(&g2);
        u1.w = *reinterpret_cast<unsigned*>(&g3);
    }
    uint4* tp = reinterpret_cast<uint4*>(tmp + (size_t)node * HDIM + jb);
    tp[0] = u0;
    tp[1] = u1;
}

// ---------------- aggregate (pure gather, padded CSR, fp16 msgs) ----------------
// 4 nodes per warp: 8-lane group per node, lane = 4 features (uint2 of half2s).
// Vectorized index loads, explicit MLP-8 gather batching, fp32 accum chains.
// OUT16: write relu(a*dis + b) as fp16 (layer 1). Else fp32 + bias + relu.

template <bool OUT16>
__global__ void __launch_bounds__(256)
agg_kernel(const uint2* __restrict__ tmp4, void* __restrict__ out,
           const float* __restrict__ b, int n)
{
    int gid  = blockIdx.x * 256 + threadIdx.x;
    int node = gid >> 3;
    int li   = threadIdx.x & 7;
    if (node >= n) return;

    int deg = g_degc[node];
    int end = deg < STRIDE ? deg : STRIDE;
    const int* row = g_csrp + (size_t)node * STRIDE;

    uint2 sv = __ldg(&tmp4[(size_t)node * 8 + li]);        // self-loop term
    float2 a0 = __half22float2(*reinterpret_cast<__half2*>(&sv.x));
    float2 a1 = __half22float2(*reinterpret_cast<__half2*>(&sv.y));

    int k = 0;
    for (; k + 8 <= end; k += 8) {
        int4 sa = __ldg(reinterpret_cast<const int4*>(&row[k]));
        int4 sb = __ldg(reinterpret_cast<const int4*>(&row[k + 4]));
        int ss[8] = {sa.x, sa.y, sa.z, sa.w, sb.x, sb.y, sb.z, sb.w};
        uint2 v[8];
#pragma unroll
        for (int j = 0; j < 8; j++) v[j] = __ldg(&tmp4[(size_t)ss[j] * 8 + li]);
#pragma unroll
        for (int j = 0; j < 8; j++) {
            float2 v0 = __half22float2(*reinterpret_cast<__half2*>(&v[j].x));
            float2 v1 = __half22float2(*reinterpret_cast<__half2*>(&v[j].y));
            a0.x += v0.x; a0.y += v0.y;
            a1.x += v1.x; a1.y += v1.y;
        }
    }
    for (; k < end; k++) {
        int ss = __ldg(&row[k]);
        uint2 v = __ldg(&tmp4[(size_t)ss * 8 + li]);
        float2 v0 = __half22float2(*reinterpret_cast<__half2*>(&v.x));
        float2 v1 = __half22float2(*reinterpret_cast<__half2*>(&v.y));
        a0.x += v0.x; a0.y += v0.y;
        a1.x += v1.x; a1.y += v1.y;
    }

    if (deg > STRIDE) {                  // overflow path: ~never taken
        int c = g_ovfc;
        for (int i = 0; i < c; i++) {
            int2 o = g_ovf[i];
            if (o.x == node) {
                uint2 v = __ldg(&tmp4[(size_t)o.y * 8 + li]);
                float2 v0 = __half22float2(*reinterpret_cast<__half2*>(&v.x));
                float2 v1 = __half22float2(*reinterpret_cast<__half2*>(&v.y));
                a0.x += v0.x; a0.y += v0.y;
                a1.x += v1.x; a1.y += v1.y;
            }
        }
    }

    float dn = g_dis[node];
    float4 bb = reinterpret_cast<const float4*>(b)[li];
    float4 r = make_float4(fmaxf(a0.x * dn + bb.x, 0.0f),
                           fmaxf(a0.y * dn + bb.y, 0.0f),
                           fmaxf(a1.x * dn + bb.z, 0.0f),
                           fmaxf(a1.y * dn + bb.w, 0.0f));
    if (OUT16) {
        __half2 h0 = __floats2half2_rn(r.x, r.y);
        __half2 h1 = __floats2half2_rn(r.z, r.w);
        uint2 u;
        u.x = *reinterpret_cast<unsigned*>(&h0);
        u.y = *reinterpret_cast<unsigned*>(&h1);
        reinterpret_cast<uint2*>(out)[(size_t)node * 8 + li] = u;
    } else {
        reinterpret_cast<float4*>(out)[(size_t)node * 8 + li] = r;
    }
}

// ---------------- launch ----------------

extern "C" void kernel_launch(void* const* d_in, const int* in_sizes, int n_in,
                              void* d_out, int out_size)
{
    const float* x   = (const float*)d_in[0];
    const void*  ei  = d_in[1];
    const float* W1  = (const float*)d_in[2];
    const float* b1  = (const float*)d_in[3];
    const float* W2  = (const float*)d_in[4];
    const float* b2  = (const float*)d_in[5];
    float*       out = (float*)d_out;

    int n = in_sizes[0] / HDIM;       // 100000
    int e = in_sizes[1] / 2;          // 1600000

    void *p_tmp, *p_acc;
    cudaGetSymbolAddress(&p_tmp, g_tmp);
    cudaGetSymbolAddress(&p_acc, g_acc16);
    uint2*  tmp4  = (uint2*)p_tmp;
    __half* tmp   = (__half*)p_tmp;
    __half* acc16 = (__half*)p_acc;

    int nb_e = (e + 255) / 256;
    int nb_m = (n + 127) / 128;               // 128 nodes per mm block
    int nb_g = (n * 8 + 255) / 256;           // 8 lanes per node

    build_kernel           <<<nb_e, 256>>>(ei, e, n);        // CSR + degrees
    mm_kernel<false, true> <<<nb_m, 256>>>(x, W1, tmp, n);   // + node prep fused
    agg_kernel<true>       <<<nb_g, 256>>>(tmp4, acc16, b1, n); // b1+relu fused here
    mm_kernel<true, false> <<<nb_m, 256>>>(acc16, W2, tmp, n);
    agg_kernel<false>      <<<nb_g, 256>>>(tmp4, out, b2, n);
}

// round 17
// speedup vs baseline: 1.1375x; 1.0276x over previous
#include <cuda_runtime.h>
#include <cuda_fp16.h>

#define NMAX   100000
#define EMAX   1600000
#define HDIM   32
#define STRIDE 64                              // padded-CSR slots per node

// Scratch (allocation-free rule: __device__ globals).
// Invariant: g_deg and g_ovfn are zero at every kernel_launch entry
// (module-load zero-init; mm1 restores after consuming them).
__device__ int    g_deg[NMAX];                 // in-degree (excl. self-loop)
__device__ int    g_degc[NMAX];                // degree copy for agg
__device__ float  g_dis[NMAX];                 // rsqrt(deg+1)
__device__ int    g_csrp[(size_t)NMAX * STRIDE]; // padded CSR: src indices
__device__ int    g_ovfn;                      // overflow count (build)
__device__ int    g_ovfc;                      // overflow count (stable copy)
__device__ int2   g_ovf[EMAX];                 // overflow (dst, src)
__device__ __half g_tmp[(size_t)NMAX * HDIM];  // messages: dis*(row@W), fp16
__device__ __half g_acc16[(size_t)NMAX * HDIM];// layer-1 output relu(..+b1), fp16

// int64 read of an int32 buffer fuses two indices -> out of [0,n) w.h.p.
__device__ __forceinline__ int detect_is32(const void* ei, int n, int* s_is32) {
    if (threadIdx.x < 32) {
        long long v = ((const long long*)ei)[threadIdx.x];
        unsigned m = __ballot_sync(0xffffffffu, v < 0 || v >= (long long)n);
        if (threadIdx.x == 0) *s_is32 = m ? 1 : 0;
    }
    __syncthreads();
    return *s_is32;
}

// ---------------- build: degree histogram + padded-CSR fill in ONE pass ----------------

__global__ void build_kernel(const void* __restrict__ ei, int e, int n) {
    __shared__ int s_is32;
    int is32 = detect_is32(ei, n, &s_is32);
    int i = blockIdx.x * blockDim.x + threadIdx.x;
    if (i >= e) return;
    int s, d;
    if (is32) {
        const int* p = (const int*)ei;
        s = p[i]; d = p[e + i];
    } else {
        const long long* p = (const long long*)ei;
        s = (int)p[i]; d = (int)p[e + i];
    }
    int pos = atomicAdd(&g_deg[d], 1);         // rank = slot (any perm ok)
    if (pos < STRIDE) {
        g_csrp[(size_t)d * STRIDE + pos] = s;
    } else {                                   // ~never on this dataset
        int k = atomicAdd(&g_ovfn, 1);
        g_ovf[k] = make_int2(d, s);
    }
}

// ---------------- mm: tmp[node] = dis[node] * (row @ W), fp16 out ----------------
// Block = 256 nodes. Rows staged in smem; each thread computes 8 outputs for
// 4 nodes (node = ns + 64*m), so every W smem load is reused 4x:
// LDS per k = 2xLDS.128 (W) + 4xLDS.32 (x) for 32 FMA  (2.8x less smem traffic).
// IN16: fp16 input rows. PREP: fused node prep (dis from g_deg, invariant restore).

template <bool IN16, bool PREP>
__global__ void __launch_bounds__(256)
mm_kernel(const void* __restrict__ in, const float* __restrict__ W,
          __half* __restrict__ tmp, int n)
{
    __shared__ float Ws[32][32];
    __shared__ float xs[256][36];          // stride 36: float4-aligned, bank-spread
    int t = threadIdx.x;
    for (int i = t; i < 1024; i += 256) Ws[i >> 5][i & 31] = W[i];

    if (PREP && blockIdx.x == 0 && t == 0) { g_ovfc = g_ovfn; g_ovfn = 0; }

    int base   = blockIdx.x * 256;
    int nvalid = n - base;
    if (nvalid > 256) nvalid = 256;

    // stage rows (coalesced)
    if (IN16) {
        const uint4* xin = reinterpret_cast<const uint4*>((const __half*)in + (size_t)base * HDIM);
        for (int i = t; i < nvalid * 4; i += 256) {   // 4 x uint4 per row
            int row = i >> 2, col = (i & 3) * 8;
            uint4 u = xin[i];
            unsigned w[4] = {u.x, u.y, u.z, u.w};
            float f[8];
#pragma unroll
            for (int j = 0; j < 4; j++) {
                float2 p = __half22float2(*reinterpret_cast<__half2*>(&w[j]));
                f[2 * j] = p.x; f[2 * j + 1] = p.y;
            }
            *reinterpret_cast<float4*>(&xs[row][col])     = make_float4(f[0], f[1], f[2], f[3]);
            *reinterpret_cast<float4*>(&xs[row][col + 4]) = make_float4(f[4], f[5], f[6], f[7]);
        }
    } else {
        const float4* xin = reinterpret_cast<const float4*>((const float*)in + (size_t)base * HDIM);
        for (int i = t; i < nvalid * 8; i += 256) {   // 8 x float4 per row
            int row = i >> 3, col = (i & 7) * 4;
            *reinterpret_cast<float4*>(&xs[row][col]) = xin[i];
        }
    }
    __syncthreads();

    int jh = t & 3;                        // output group: jb = jh*8
    int ns = t >> 2;                       // 0..63; nodes ns, ns+64, ns+128, ns+192
    int jb = jh * 8;

    float o[4][8];
#pragma unroll
    for (int m = 0; m < 4; m++)
#pragma unroll
        for (int j = 0; j < 8; j++) o[m][j] = 0.0f;

#pragma unroll
    for (int k = 0; k < 32; k++) {
        float4 wa = *reinterpret_cast<const float4*>(&Ws[k][jb]);
        float4 wb = *reinterpret_cast<const float4*>(&Ws[k][jb + 4]);
#pragma unroll
        for (int m = 0; m < 4; m++) {
            float xv = xs[ns + 64 * m][k];
            o[m][0] = fmaf(xv, wa.x, o[m][0]);
            o[m][1] = fmaf(xv, wa.y, o[m][1]);
            o[m][2] = fmaf(xv, wa.z, o[m][2]);
            o[m][3] = fmaf(xv, wa.w, o[m][3]);
            o[m][4] = fmaf(xv, wb.x, o[m][4]);
            o[m][5] = fmaf(xv, wb.y, o[m][5]);
            o[m][6] = fmaf(xv, wb.z, o[m][6]);
            o[m][7] = fmaf(xv, wb.w, o[m][7]);
        }
    }

#pragma unroll
    for (int m = 0; m < 4; m++) {
        int nl = ns + 64 * m;
        if (nl >= nvalid) continue;
        int node = base + nl;

        float dn;
        if (PREP) {
            int degv = g_deg[node];
            dn = rsqrtf((float)(degv + 1));    // +1: self-loop
            if (jh == 0) {
                g_dis[node]  = dn;
                g_degc[node] = degv;
                g_deg[node]  = 0;              // restore invariant for next call
            }
        } else {
            dn = g_dis[node];
        }

        __half2 h0 = __floats2half2_rn(o[m][0] * dn, o[m][1] * dn);
        __half2 h1 = __floats2half2_rn(o[m][2] * dn, o[m][3] * dn);
        __half2 h2 = __floats2half2_rn(o[m][4] * dn, o[m][5] * dn);
        __half2 h3 = __floats2half2_rn(o[m][6] * dn, o[m][7] * dn);
        uint4 u;
        u.x = *reinterpret_cast<unsigned*>(&h0);
        u.y = *reinterpret_cast<unsigned*>(&h1);
        u.z = *reinterpret_cast<unsigned*>(&h2);
        u.w = *reinterpret_cast<unsigned*>(&h3);
        *reinterpret_cast<uint4*>(tmp + (size_t)node * HDIM + jb) = u;
    }
}

// ---------------- aggregate (pure gather, padded CSR, fp16 msgs) ----------------
// 4 nodes per warp: 8-lane group per node, lane = 4 features (uint2 of half2s).
// Vectorized index loads, explicit MLP-8 gather batching, fp32 accum chains.
// OUT16: write relu(a*dis + b) as fp16 (layer 1). Else fp32 + bias + relu.

template <bool OUT16>
__global__ void __launch_bounds__(256)
agg_kernel(const uint2* __restrict__ tmp4, void* __restrict__ out,
           const float* __restrict__ b, int n)
{
    int gid  = blockIdx.x * 256 + threadIdx.x;
    int node = gid >> 3;
    int li   = threadIdx.x & 7;
    if (node >= n) return;

    int deg = g_degc[node];
    int end = deg < STRIDE ? deg : STRIDE;
    const int* row = g_csrp + (size_t)node * STRIDE;

    uint2 sv = __ldg(&tmp4[(size_t)node * 8 + li]);        // self-loop term
    float2 a0 = __half22float2(*reinterpret_cast<__half2*>(&sv.x));
    float2 a1 = __half22float2(*reinterpret_cast<__half2*>(&sv.y));

    int k = 0;
    for (; k + 8 <= end; k += 8) {
        int4 sa = __ldg(reinterpret_cast<const int4*>(&row[k]));
        int4 sb = __ldg(reinterpret_cast<const int4*>(&row[k + 4]));
        int ss[8] = {sa.x, sa.y, sa.z, sa.w, sb.x, sb.y, sb.z, sb.w};
        uint2 v[8];
#pragma unroll
        for (int j = 0; j < 8; j++) v[j] = __ldg(&tmp4[(size_t)ss[j] * 8 + li]);
#pragma unroll
        for (int j = 0; j < 8; j++) {
            float2 v0 = __half22float2(*reinterpret_cast<__half2*>(&v[j].x));
            float2 v1 = __half22float2(*reinterpret_cast<__half2*>(&v[j].y));
            a0.x += v0.x; a0.y += v0.y;
            a1.x += v1.x; a1.y += v1.y;
        }
    }
    for (; k < end; k++) {
        int ss = __ldg(&row[k]);
        uint2 v = __ldg(&tmp4[(size_t)ss * 8 + li]);
        float2 v0 = __half22float2(*reinterpret_cast<__half2*>(&v.x));
        float2 v1 = __half22float2(*reinterpret_cast<__half2*>(&v.y));
        a0.x += v0.x; a0.y += v0.y;
        a1.x += v1.x; a1.y += v1.y;
    }

    if (deg > STRIDE) {                  // overflow path: ~never taken
        int c = g_ovfc;
        for (int i = 0; i < c; i++) {
            int2 o = g_ovf[i];
            if (o.x == node) {
                uint2 v = __ldg(&tmp4[(size_t)o.y * 8 + li]);
                float2 v0 = __half22float2(*reinterpret_cast<__half2*>(&v.x));
                float2 v1 = __half22float2(*reinterpret_cast<__half2*>(&v.y));
                a0.x += v0.x; a0.y += v0.y;
                a1.x += v1.x; a1.y += v1.y;
            }
        }
    }

    float dn = g_dis[node];
    float4 bb = reinterpret_cast<const float4*>(b)[li];
    float4 r = make_float4(fmaxf(a0.x * dn + bb.x, 0.0f),
                           fmaxf(a0.y * dn + bb.y, 0.0f),
                           fmaxf(a1.x * dn + bb.z, 0.0f),
                           fmaxf(a1.y * dn + bb.w, 0.0f));
    if (OUT16) {
        __half2 h0 = __floats2half2_rn(r.x, r.y);
        __half2 h1 = __floats2half2_rn(r.z, r.w);
        uint2 u;
        u.x = *reinterpret_cast<unsigned*>(&h0);
        u.y = *reinterpret_cast<unsigned*>(&h1);
        reinterpret_cast<uint2*>(out)[(size_t)node * 8 + li] = u;
    } else {
        reinterpret_cast<float4*>(out)[(size_t)node * 8 + li] = r;
    }
}

// ---------------- launch ----------------

extern "C" void kernel_launch(void* const* d_in, const int* in_sizes, int n_in,
                              void* d_out, int out_size)
{
    const float* x   = (const float*)d_in[0];
    const void*  ei  = d_in[1];
    const float* W1  = (const float*)d_in[2];
    const float* b1  = (const float*)d_in[3];
    const float* W2  = (const float*)d_in[4];
    const float* b2  = (const float*)d_in[5];
    float*       out = (float*)d_out;

    int n = in_sizes[0] / HDIM;       // 100000
    int e = in_sizes[1] / 2;          // 1600000

    void *p_tmp, *p_acc;
    cudaGetSymbolAddress(&p_tmp, g_tmp);
    cudaGetSymbolAddress(&p_acc, g_acc16);
    uint2*  tmp4  = (uint2*)p_tmp;
    __half* tmp   = (__half*)p_tmp;
    __half* acc16 = (__half*)p_acc;

    int nb_e = (e + 255) / 256;
    int nb_m = (n + 255) / 256;               // 256 nodes per mm block
    int nb_g = (n * 8 + 255) / 256;           // 8 lanes per node

    build_kernel           <<<nb_e, 256>>>(ei, e, n);        // CSR + degrees
    mm_kernel<false, true> <<<nb_m, 256>>>(x, W1, tmp, n);   // + node prep fused
    agg_kernel<true>       <<<nb_g, 256>>>(tmp4, acc16, b1, n); // b1+relu fused
    mm_kernel<true, false> <<<nb_m, 256>>>(acc16, W2, tmp, n);
    agg_kernel<false>      <<<nb_g, 256>>>(tmp4, out, b2, n);
}